// round 17
// baseline (speedup 1.0000x reference)
#include <cuda_runtime.h>
#include <cuda_fp16.h>
#include <cstdint>

// ---------------- problem constants ----------------
#define BS      2
#define C_IN    64
#define NA      60
#define KS      3
#define ANN     8
#define C_OUT   128
#define K_DIM   192              // C_IN*KS
#define NPAIRS  180              // NA*KS
#define NP      1024
#define NJOBS   (BS * NP)        // 2048

#define NTHREADS 256
#define GRID_CTAS 592            // 4 per SM x 148 SMs

#define KSTEPS  12               // 192 / 16
#define NTILES  8                // 64 / 8

// ---------------- SMEM layout (bytes) ----------------
// B fragments (fp16): unit (nt,ks,lane) = 8B {b0: k0,k0+1 | b1: k0+8,k0+9}
#define B_BYTES     (NTILES * KSTEPS * 32 * 8)       // 24576
#define SMEM_B      0
// feats slab as packed half2(c, c+32): [cp 32][61 u32]
#define FPADH       61
#define SMEM_FH     B_BYTES                          // 24576
#define FH_BYTES    (32 * FPADH * 4)                 // 7808
#define SMEM_IDX    (SMEM_FH + FH_BYTES)             // 32384 (16B aligned)
#define SMEM_WH     (SMEM_IDX + NPAIRS * ANN * 4)    // 38144
#define SMEM_TOTAL  (SMEM_WH + NPAIRS * ANN * 4)     // 43904 (x4 = 175616)

// ---------------- A fragments (W, fp16) in m16n8k16 per-lane order ----------------
// [mtile 8][kstep 12][lane 32][4 x b32]  -> 48 KB (L1-resident)
__device__ __align__(16) uint32_t Afrag_g[8 * KSTEPS * 32 * 4];

__global__ void pack_W_kernel(const float* __restrict__ Wmat) {
    int t = blockIdx.x * 256 + threadIdx.x;          // t = (mt*12+ks)*32+lane
    if (t >= 8 * KSTEPS * 32) return;
    const int lane = t & 31;
    const int ks   = (t >> 5) % KSTEPS;
    const int mt   = (t >> 5) / KSTEPS;
    const int r0 = mt * 16 + (lane >> 2);
    const int k0 = ks * 16 + ((lane & 3) << 1);
    uint32_t regs[4];
    #pragma unroll
    for (int reg = 0; reg < 4; reg++) {
        const int r = r0 + ((reg & 1) ? 8 : 0);
        const int k = k0 + ((reg & 2) ? 8 : 0);
        const __half h0 = __float2half_rn(Wmat[r * K_DIM + k]);
        const __half h1 = __float2half_rn(Wmat[r * K_DIM + k + 1]);
        regs[reg] = (uint32_t)__half_as_ushort(h0) |
                    ((uint32_t)__half_as_ushort(h1) << 16);
    }
    *(uint4*)(Afrag_g + (size_t)t * 4) = make_uint4(regs[0], regs[1], regs[2], regs[3]);
}

// byte offset of the u16 for logical (o = n index, kc = k index)
__device__ __forceinline__ uint32_t bfrag_off16(int o, int kc) {
    const uint32_t blane = (uint32_t)(((o & 7) << 2) | ((kc >> 1) & 3));
    const uint32_t unit  = (uint32_t)(((o >> 3) * KSTEPS + (kc >> 4)) * 32) + blane;
    return (unit << 3) + ((((uint32_t)kc >> 3) & 1) << 2) + (((uint32_t)kc & 1) << 1);
}

__device__ __forceinline__ uint32_t smem_u32(const void* p) {
    uint32_t a;
    asm("{ .reg .u64 t; cvta.to.shared.u64 t, %1; cvt.u32.u64 %0, t; }" : "=r"(a) : "l"(p));
    return a;
}

// ---------------- main fused kernel (persistent, 4 CTAs/SM) ----------------
__global__ __launch_bounds__(NTHREADS, 4)
void intrazp_mma_kernel(const float* __restrict__ feats,
                        const float* __restrict__ intra_w,
                        const float* __restrict__ bias,
                        const int*   __restrict__ intra_idx,
                        float* __restrict__ out)
{
    extern __shared__ char smem[];
    const uint32_t smb = smem_u32(smem);
    uint32_t* FsmH = (uint32_t*)(smem + SMEM_FH);    // [cp][61], half2(c, c+32)
    int*      Ism  = (int*)     (smem + SMEM_IDX);
    uint32_t* Whsm = (uint32_t*)(smem + SMEM_WH);    // half2(w, w) per (pr, a)
    const int tid = threadIdx.x, wid = tid >> 5, lane = tid & 31;

    // warp tiling for GEMM: 4M x 2N
    const int mq = wid & 3, nq = wid >> 2;

    // ---- one-time: zero B pad rows (o = 60..63), cache idx / broadcast-half2 w ----
    for (int t = tid; t < 4 * K_DIM; t += NTHREADS) {
        const int o = 60 + t / K_DIM, kc = t % K_DIM;
        asm volatile("st.shared.u16 [%0], %1;"
                     :: "r"(smb + SMEM_B + bfrag_off16(o, kc)), "h"((unsigned short)0));
    }
    for (int t = tid; t < NPAIRS * ANN; t += NTHREADS) {
        Ism[t] = __ldg(intra_idx + t);
        const unsigned short wh = __half_as_ushort(__float2half_rn(__ldg(intra_w + t)));
        Whsm[t] = (uint32_t)wh | ((uint32_t)wh << 16);
    }

    // bias for the 4 row-groups this thread accumulates
    const int rb = mq * 32 + (lane >> 2);
    float bv[4];
    #pragma unroll
    for (int i = 0; i < 4; i++) bv[i] = __ldg(bias + rb + i * 8);
    __syncthreads();

    for (int job = blockIdx.x; job < NJOBS; job += GRID_CTAS) {
        const int b = job >> 10, p = job & (NP - 1);

        // ---- load feats: rows c and c+32, pack into half2 slab ----
        for (int t = tid; t < 32 * 15; t += NTHREADS) {
            const int c = t / 15, q = t - c * 15;
            const float* base = feats + (((size_t)b * C_IN + c) * NP + p) * NA;
            const float4 v0 = __ldg((const float4*)base + q);
            const float4 v1 = __ldg((const float4*)(base + (size_t)32 * NP * NA) + q);
            uint32_t* dst = FsmH + c * FPADH + q * 4;
            dst[0] = (uint32_t)__half_as_ushort(__float2half_rn(v0.x)) |
                     ((uint32_t)__half_as_ushort(__float2half_rn(v1.x)) << 16);
            dst[1] = (uint32_t)__half_as_ushort(__float2half_rn(v0.y)) |
                     ((uint32_t)__half_as_ushort(__float2half_rn(v1.y)) << 16);
            dst[2] = (uint32_t)__half_as_ushort(__float2half_rn(v0.z)) |
                     ((uint32_t)__half_as_ushort(__float2half_rn(v1.z)) << 16);
            dst[3] = (uint32_t)__half_as_ushort(__float2half_rn(v0.w)) |
                     ((uint32_t)__half_as_ushort(__float2half_rn(v1.w)) << 16);
        }
        __syncthreads();

        // ---- stage A: gather-reduce in half2 (both c-halves per HFMA2) ----
        for (int pr = wid; pr < NPAIRS; pr += 8) {
            const int o = pr / KS, kk = pr - o * KS;
            const int4  ia = *(const int4*) (Ism  + pr * ANN);
            const int4  ib = *((const int4*)(Ism  + pr * ANN) + 1);
            const uint4 wa = *(const uint4*)(Whsm + pr * ANN);
            const uint4 wb = *((const uint4*)(Whsm + pr * ANN) + 1);
            const uint32_t* fr = FsmH + lane * FPADH;

            // two 4-term chains, then one hadd2 (precision guard)
            __half2 acc0, acc1;
            acc0 = __hmul2(*(const __half2*)&fr[ia.x], *(const __half2*)&wa.x);
            acc0 = __hfma2(*(const __half2*)&fr[ia.y], *(const __half2*)&wa.y, acc0);
            acc0 = __hfma2(*(const __half2*)&fr[ia.z], *(const __half2*)&wa.z, acc0);
            acc0 = __hfma2(*(const __half2*)&fr[ia.w], *(const __half2*)&wa.w, acc0);
            acc1 = __hmul2(*(const __half2*)&fr[ib.x], *(const __half2*)&wb.x);
            acc1 = __hfma2(*(const __half2*)&fr[ib.y], *(const __half2*)&wb.y, acc1);
            acc1 = __hfma2(*(const __half2*)&fr[ib.z], *(const __half2*)&wb.z, acc1);
            acc1 = __hfma2(*(const __half2*)&fr[ib.w], *(const __half2*)&wb.w, acc1);
            const __half2 s = __hadd2(acc0, acc1);
            const uint32_t av = *(const uint32_t*)&s;

            // c = lane -> off; c = lane+32 -> off + 1536 (kc shift of 96 = 6*16)
            const uint32_t off = smb + SMEM_B + bfrag_off16(o, lane * KS + kk);
            asm volatile("st.shared.u16 [%0], %1;"
                         :: "r"(off), "h"((unsigned short)(av & 0xFFFF)));
            asm volatile("st.shared.u16 [%0], %1;"
                         :: "r"(off + 1536), "h"((unsigned short)(av >> 16)));
        }
        __syncthreads();

        // ---- GEMM: single-pass fp16 m16n8k16, warp tile 32M x 32N ----
        float acc[2][4][4];
        #pragma unroll
        for (int mt = 0; mt < 2; mt++)
            #pragma unroll
            for (int j = 0; j < 4; j++) {
                acc[mt][j][0] = bv[2 * mt];     acc[mt][j][1] = bv[2 * mt];
                acc[mt][j][2] = bv[2 * mt + 1]; acc[mt][j][3] = bv[2 * mt + 1];
            }

        const int mt0 = 2 * mq;
        #pragma unroll 4
        for (int ks = 0; ks < KSTEPS; ks++) {
            uint4 af[2];
            #pragma unroll
            for (int mt = 0; mt < 2; mt++)
                af[mt] = __ldg((const uint4*)Afrag_g + ((mt0 + mt) * KSTEPS + ks) * 32 + lane);
            #pragma unroll
            for (int j = 0; j < 4; j++) {
                const int nt = nq * 4 + j;
                uint32_t b0, b1;
                asm volatile("ld.shared.v2.b32 {%0,%1}, [%2];"
                             : "=r"(b0), "=r"(b1)
                             : "r"(smb + SMEM_B + (uint32_t)(((nt * KSTEPS + ks) * 32 + lane) << 3)));
                #pragma unroll
                for (int mt = 0; mt < 2; mt++) {
                    asm volatile(
                        "mma.sync.aligned.m16n8k16.row.col.f32.f16.f16.f32 "
                        "{%0,%1,%2,%3}, {%4,%5,%6,%7}, {%8,%9}, {%0,%1,%2,%3};"
                        : "+f"(acc[mt][j][0]), "+f"(acc[mt][j][1]),
                          "+f"(acc[mt][j][2]), "+f"(acc[mt][j][3])
                        : "r"(af[mt].x), "r"(af[mt].y), "r"(af[mt].z), "r"(af[mt].w),
                          "r"(b0), "r"(b1));
                }
            }
        }

        // ---- epilogue: store rows (2 mtiles x 2 row-groups), cols 32*nq..+31 ----
        {
            const int ncol = nq * 32 + (lane & 3) * 2;
            #pragma unroll
            for (int mt = 0; mt < 2; mt++) {
                const int r1 = mq * 32 + mt * 16 + (lane >> 2);
                float* orow1 = out + (((size_t)(b * C_OUT + r1)) * NP + p) * NA;
                float* orow2 = orow1 + (size_t)8 * NP * NA;
                #pragma unroll
                for (int j = 0; j < 4; j++) {
                    const int n = ncol + j * 8;
                    if (n < NA) {
                        *(float2*)(orow1 + n) = make_float2(acc[mt][j][0], acc[mt][j][1]);
                        *(float2*)(orow2 + n) = make_float2(acc[mt][j][2], acc[mt][j][3]);
                    }
                }
            }
        }
        __syncthreads();   // protect FsmH/B before next job
    }
}

extern "C" void kernel_launch(void* const* d_in, const int* in_sizes, int n_in,
                              void* d_out, int out_size)
{
    const float* feats     = (const float*)d_in[0];  // (2,64,1024,60) f32
    const float* intra_w   = (const float*)d_in[1];  // (60,3,8)       f32
    const float* Wmat      = (const float*)d_in[2];  // (128,192)      f32
    const float* bias      = (const float*)d_in[3];  // (1,128,1)      f32
    const int*   intra_idx = (const int*)  d_in[4];  // (60,3,8)       i32
    float* out = (float*)d_out;                      // (2,128,1024,60) f32

    cudaFuncSetAttribute(intrazp_mma_kernel,
                         cudaFuncAttributeMaxDynamicSharedMemorySize, SMEM_TOTAL);

    pack_W_kernel<<<(8 * KSTEPS * 32 + 255) / 256, 256>>>(Wmat);
    intrazp_mma_kernel<<<GRID_CTAS, NTHREADS, SMEM_TOTAL>>>(
        feats, intra_w, bias, intra_idx, out);
}